// round 14
// baseline (speedup 1.0000x reference)
#include <cuda_runtime.h>
#include <stdint.h>

// NeighborNoiser — partitionable threefry2x32, key (0,42), fold = x0^x1 (bit-exact R2+).
// R14: alu-drain experiment. All threefry mix/schedule adds forced onto the fma
// pipe as IMAD via mad.lo.u32 with an OPAQUE runtime 1 multiplier (ptxas cannot
// strength-reduce). alu keeps only SHF+LOP3 (obligate). Slots +~6% (unfused
// 3-input adds); discriminates alu-pipe cap (-> ~238us) vs universal issue pin
// (-> ~260us, revert to R13).

#define N1 25165824u                    // 8*3*1024*1024

__device__ __forceinline__ uint32_t rotl(uint32_t v, const int d) {
    return __funnelshift_l(v, v, d);
}

// d = a + c, forced IMAD (fma pipe): a*one + c with runtime-opaque one==1
#define MADD(d_, a_, c_) \
    asm("mad.lo.u32 %0, %1, %2, %3;" : "=r"(d_) : "r"(a_), "r"(one), "r"(c_))
// d = c + IMM, forced IMAD: one*IMM + c
#define ADDI(d_, imm_, c_) \
    asm("mad.lo.u32 %0, %1, %2, %3;" : "=r"(d_) : "r"(one), "n"(imm_), "r"(c_))

// one round: x0 += x1 (IMAD);  x1 = rotl(x1,d) ^ x0 (SHF+LOP3, alu)
#define RSM(d_) { MADD(x0, x1, x0); x1 = rotl(x1,(d_)) ^ x0; }

// threefry2x32, key (0,42), counter (0,ctr); all adds on fma pipe.
__device__ __forceinline__ uint32_t tf_imad(uint32_t ctr, uint32_t one) {
    const uint32_t ks1 = 42u, ks2 = 0x1BD11BDAu ^ 42u;
    uint32_t x0, x1;
    ADDI(x1, 42u, ctr);                 // x1 = ctr + ks1
    x0 = x1;                            // round-1 add with x0 = 0
    x1 = rotl(x1,13) ^ x0;
    RSM(15) RSM(26) RSM(6)
    ADDI(x1, (0x1BD11BDAu ^ 42u) + 1u, x1);    // x1 += ks2 + 1
    MADD(x0, x1, x0); ADDI(x0, 42u, x0);       // x0 += x1 + ks1 (unfused)
    x1 = rotl(x1,17) ^ x0;
    RSM(29) RSM(16) RSM(24)
    ADDI(x1, 2u, x1);                          // x1 += ks0 + 2
    MADD(x0, x1, x0); ADDI(x0, (0x1BD11BDAu ^ 42u), x0);  // x0 += x1 + ks2
    x1 = rotl(x1,13) ^ x0;
    RSM(15) RSM(26) RSM(6)
    ADDI(x1, 42u + 3u, x1);                    // x1 += ks1 + 3
    MADD(x0, x1, x0);                          // x0 += x1  (ks0 = 0)
    x1 = rotl(x1,17) ^ x0;
    RSM(29) RSM(16) RSM(24)
    ADDI(x1, (0x1BD11BDAu ^ 42u) + 4u, x1);    // x1 += ks2 + 4
    MADD(x0, x1, x0); ADDI(x0, 42u, x0);       // x0 += x1 + ks1
    x1 = rotl(x1,13) ^ x0;
    RSM(15) RSM(26) RSM(6)
    ADDI(x1, 5u, x1);                          // x1 += ks0 + 5
    ADDI(x0, (0x1BD11BDAu ^ 42u), x0);         // x0 += ks2
    (void)ks1; (void)ks2;
    return x0 ^ x1;                            // fold (LOP3)
}

// Single IMAD.HI (fma pipe): hi(bits * 2^23) + 0x3f800000 -> [1,2); then -1.
__device__ __forceinline__ float u01(uint32_t bits) {
    uint32_t m;
    asm("mad.hi.u32 %0, %1, %2, %3;"
        : "=r"(m) : "r"(bits), "r"(1u << 23), "r"(0x3f800000u));
    return __uint_as_float(m) - 1.0f;
}

__global__ __launch_bounds__(256, 6)
void neighbor_noiser_kernel(const float* __restrict__ t, float* __restrict__ out) {
    uint32_t gid  = blockIdx.x * blockDim.x + threadIdx.x;
    // opaque 1: gid cannot be proven < 2^31 at compile time (blockIdx unknown),
    // but is ~6.3M at runtime -> one == 1 always.
    uint32_t one  = (gid >> 31) + 1u;
    uint32_t base = gid * 4u;                   // 4 adjacent pixels in one row

    uint32_t plane = base >> 20;
    uint32_t pos   = base & 0xFFFFFu;
    uint32_t y     = pos >> 10;
    uint32_t x     = pos & 1023u;               // multiple of 4

    const float* p = t + ((size_t)plane << 20);
    uint32_t yu = (y == 0u)    ? 0u    : y - 1u;
    uint32_t yd = (y == 1023u) ? 1023u : y + 1u;
    const float* rowc = p + (y << 10);

    float4 up4 = __ldg((const float4*)(p + (yu << 10) + x));
    float4 dn4 = __ldg((const float4*)(p + (yd << 10) + x));
    float4 ct4 = __ldg((const float4*)(rowc + x));
    float lf_e = (x == 0u)     ? ct4.x : __ldg(rowc + x - 1u);
    float rt_e = (x == 1020u)  ? ct4.w : __ldg(rowc + x + 4u);

    // 16 independent chains, SHF rotates on alu, ALL adds as IMAD on fma
    uint32_t bu0 = tf_imad(base,            one);
    uint32_t bu1 = tf_imad(base + 1u,       one);
    uint32_t bu2 = tf_imad(base + 2u,       one);
    uint32_t bu3 = tf_imad(base + 3u,       one);
    uint32_t bd0 = tf_imad(base + N1,       one);
    uint32_t bd1 = tf_imad(base + N1 + 1u,  one);
    uint32_t bd2 = tf_imad(base + N1 + 2u,  one);
    uint32_t bd3 = tf_imad(base + N1 + 3u,  one);
    uint32_t bl0 = tf_imad(base + 2u*N1,      one);
    uint32_t bl1 = tf_imad(base + 2u*N1 + 1u, one);
    uint32_t bl2 = tf_imad(base + 2u*N1 + 2u, one);
    uint32_t bl3 = tf_imad(base + 2u*N1 + 3u, one);
    uint32_t br0 = tf_imad(base + 3u*N1,      one);
    uint32_t br1 = tf_imad(base + 3u*N1 + 1u, one);
    uint32_t br2 = tf_imad(base + 3u*N1 + 2u, one);
    uint32_t br3 = tf_imad(base + 3u*N1 + 3u, one);

    float upv[4] = {up4.x, up4.y, up4.z, up4.w};
    float dnv[4] = {dn4.x, dn4.y, dn4.z, dn4.w};
    float lfv[4] = {lf_e,  ct4.x, ct4.y, ct4.z};
    float rtv[4] = {ct4.y, ct4.z, ct4.w, rt_e};
    uint32_t buv[4] = {bu0, bu1, bu2, bu3};
    uint32_t bdv[4] = {bd0, bd1, bd2, bd3};
    uint32_t blv[4] = {bl0, bl1, bl2, bl3};
    uint32_t brv[4] = {br0, br1, br2, br3};

    float res[4];
#pragma unroll
    for (int i = 0; i < 4; i++) {
        float ur = u01(buv[i]);
        float dr = u01(bdv[i]);
        float lr = u01(blv[i]);
        float rr = u01(brv[i]);
        float s   = (ur + dr) + (lr + rr);
        float num = fmaf(upv[i], ur, fmaf(dnv[i], dr, fmaf(lfv[i], lr, rtv[i] * rr)));
        res[i] = __fdividef(num, s);
    }

    *reinterpret_cast<float4*>(out + base) = make_float4(res[0], res[1], res[2], res[3]);
}

extern "C" void kernel_launch(void* const* d_in, const int* in_sizes, int n_in,
                              void* d_out, int out_size) {
    const float* t = (const float*)d_in[0];
    float* out = (float*)d_out;
    (void)in_sizes; (void)n_in; (void)out_size;

    const uint32_t threads = 256;
    const uint32_t blocks = (N1 / 4u) / threads;   // 24576, exact
    neighbor_noiser_kernel<<<blocks, threads>>>(t, out);
}

// round 15
// speedup vs baseline: 1.7837x; 1.7837x over previous
#include <cuda_runtime.h>
#include <stdint.h>

// NeighborNoiser — partitionable threefry2x32, key (0,42), fold = x0^x1 (bit-exact R2+).
// R15 = R13 (best: 248.3us, pure-SHF, 4px/thread, launch_bounds(256,6)) with the
// per-pixel epilogues INTERLEAVED between hash sections. R13's trailing 4-epilogue
// block is ~68 pure-fma slots/thread during which the alu pipe (the binding
// resource, 93.9% busy) idles. Burying 3 of 4 epilogues inside alu-dense hash
// code targets alu busy -> ~97%, dur -> ~241us. Slot count unchanged.

#define N1 25165824u                    // 8*3*1024*1024

__device__ __forceinline__ uint32_t rotl(uint32_t v, const int d) {
    return __funnelshift_l(v, v, d);
}

#define RS(d) { x0 += x1; x1 = rotl(x1,(d)) ^ x0; }

// SHF-rotate threefry chain, IADD3-fused key schedule
__device__ __forceinline__ uint32_t tf_shf(uint32_t ctr) {
    const uint32_t ks1 = 42u, ks2 = 0x1BD11BDAu ^ 42u;
    uint32_t x1 = ctr + ks1;
    uint32_t x0 = x1;                               // round-1 add with x0 = 0
    x1 = rotl(x1,13) ^ x0;
    RS(15) RS(26) RS(6)
    x1 += ks2 + 1u;  x0 = x0 + x1 + ks1;  x1 = rotl(x1,17) ^ x0;
    RS(29) RS(16) RS(24)
    x1 += 2u;        x0 = x0 + x1 + ks2;  x1 = rotl(x1,13) ^ x0;
    RS(15) RS(26) RS(6)
    x1 += ks1 + 3u;  x0 = x0 + x1;        x1 = rotl(x1,17) ^ x0;   // ks0 = 0
    RS(29) RS(16) RS(24)
    x1 += ks2 + 4u;  x0 = x0 + x1 + ks1;  x1 = rotl(x1,13) ^ x0;
    RS(15) RS(26) RS(6)
    x1 += 5u;
    return (x0 + ks2) ^ x1;
}

// Single IMAD.HI (fma pipe): hi(bits * 2^23) + 0x3f800000 -> [1,2); then -1.
__device__ __forceinline__ float u01(uint32_t bits) {
    uint32_t m;
    asm("mad.hi.u32 %0, %1, %2, %3;"
        : "=r"(m) : "r"(bits), "r"(1u << 23), "r"(0x3f800000u));
    return __uint_as_float(m) - 1.0f;
}

// epilogue for one pixel
__device__ __forceinline__ float pixel_out(uint32_t bu, uint32_t bd, uint32_t bl,
                                           uint32_t br, float up, float dn,
                                           float lf, float rt) {
    float ur = u01(bu);
    float dr = u01(bd);
    float lr = u01(bl);
    float rr = u01(br);
    float s   = (ur + dr) + (lr + rr);
    float num = fmaf(up, ur, fmaf(dn, dr, fmaf(lf, lr, rt * rr)));
    return __fdividef(num, s);
}

// all 4 chains of one pixel
#define PX_CHAINS(k, j)                      \
    uint32_t bu##k = tf_shf(j);              \
    uint32_t bd##k = tf_shf((j) + N1);       \
    uint32_t bl##k = tf_shf((j) + 2u*N1);    \
    uint32_t br##k = tf_shf((j) + 3u*N1);

__global__ __launch_bounds__(256, 6)
void neighbor_noiser_kernel(const float* __restrict__ t, float* __restrict__ out) {
    uint32_t gid  = blockIdx.x * blockDim.x + threadIdx.x;
    uint32_t base = gid * 4u;                   // 4 adjacent pixels in one row

    uint32_t plane = base >> 20;
    uint32_t pos   = base & 0xFFFFFu;
    uint32_t y     = pos >> 10;
    uint32_t x     = pos & 1023u;               // multiple of 4

    const float* p = t + ((size_t)plane << 20);
    uint32_t yu = (y == 0u)    ? 0u    : y - 1u;
    uint32_t yd = (y == 1023u) ? 1023u : y + 1u;
    const float* rowc = p + (y << 10);

    float4 up4 = __ldg((const float4*)(p + (yu << 10) + x));
    float4 dn4 = __ldg((const float4*)(p + (yd << 10) + x));
    float4 ct4 = __ldg((const float4*)(rowc + x));
    float lf_e = (x == 0u)     ? ct4.x : __ldg(rowc + x - 1u);
    float rt_e = (x == 1020u)  ? ct4.w : __ldg(rowc + x + 4u);

    float res0, res1, res2, res3;

    // interleave: hash px0, hash px1, epi px0, hash px2, epi px1,
    //             hash px3, epi px2, epi px3  — fma epilogues hide
    //             inside alu-dense hash sections.
    {
        PX_CHAINS(0, base)
        PX_CHAINS(1, base + 1u)
        res0 = pixel_out(bu0, bd0, bl0, br0, up4.x, dn4.x, lf_e,  ct4.y);
        PX_CHAINS(2, base + 2u)
        res1 = pixel_out(bu1, bd1, bl1, br1, up4.y, dn4.y, ct4.x, ct4.z);
        PX_CHAINS(3, base + 3u)
        res2 = pixel_out(bu2, bd2, bl2, br2, up4.z, dn4.z, ct4.y, ct4.w);
        res3 = pixel_out(bu3, bd3, bl3, br3, up4.w, dn4.w, ct4.z, rt_e);
    }

    *reinterpret_cast<float4*>(out + base) = make_float4(res0, res1, res2, res3);
}

extern "C" void kernel_launch(void* const* d_in, const int* in_sizes, int n_in,
                              void* d_out, int out_size) {
    const float* t = (const float*)d_in[0];
    float* out = (float*)d_out;
    (void)in_sizes; (void)n_in; (void)out_size;

    const uint32_t threads = 256;
    const uint32_t blocks = (N1 / 4u) / threads;   // 24576, exact
    neighbor_noiser_kernel<<<blocks, threads>>>(t, out);
}